// round 12
// baseline (speedup 1.0000x reference)
#include <cuda_runtime.h>
#include <cstdint>

// Problem constants
#define BB 64       // batch
#define KK 4096     // dim_in
#define OO 4096     // dim_out
#define NBLK 256    // blocks (all resident: 256 <= 148*2 guaranteed at <=255 regs)
#define NSLAB 8     // k-slabs (512 k each)
#define NOMEGA 128  // o-blocks of 32 columns
#define TILES 16    // 32-row kw-tiles per slab

// x bits: [kw][b]
__device__ uint32_t g_xbitsT[(KK / 32) * BB];        // 32 KB
// packed partial popc sums: [(slab*32 + batch-pair)][o], 16-bit halves
__device__ uint32_t g_partial[NSLAB * 32 * OO];      // 4 MB
// grid sync state (self-resetting every launch; zero at load)
__device__ int g_pack_arrive;
__device__ int g_pack_exit;
__device__ int g_ocnt[NOMEGA];

// Robust 0/1 extraction: int32 {0,1} (bit 0) or float32 {0.0f,1.0f} (bit 23).
__device__ __forceinline__ uint32_t bit01(uint32_t w) {
    return (w | (w >> 23)) & 1u;
}

// ---------------------------------------------------------------------------
// One fused kernel: 256 blocks x 128 threads (1024 warps).
// Warp wg -> (omega = wg & 127 : 32 columns via lanes, slab = wg >> 7).
// Per warp: 16 tiles of [32 k x 32 o] bits:
//   coalesced row loads -> ballot -> in-register bit transpose -> popc vs all
//   64 batches (16-bit packed accumulators), next-tile loads prefetched.
// No smem, no block barriers in the mainloop: DRAM and ALU overlap per-warp.
// ---------------------------------------------------------------------------
__global__ void __launch_bounds__(128) xnor_bitgemm_kernel(
    const uint32_t* __restrict__ x,       // [BB][KK] 0/1 words
    const uint32_t* __restrict__ masks,   // [KK][OO] 0/1 words
    const int*      __restrict__ thr,     // [OO] int32
    float*          __restrict__ out)     // [BB][OO] float32 0/1
{
    const int t     = threadIdx.x;
    const int lane  = t & 31;
    const int wid   = t >> 5;
    const int wg    = blockIdx.x * 4 + wid;
    const int omega = wg & (NOMEGA - 1);
    const int slab  = wg >> 7;
    const int o     = omega * 32 + lane;

    // ---------------- pack x: each block ballots its 1024-element slice ----
    {
        const int base = blockIdx.x * 1024;
        #pragma unroll
        for (int i = 0; i < 8; i++) {
            const int g = base + i * 128 + t;       // element id -> (b, k)
            uint32_t w = __ballot_sync(0xFFFFFFFFu, bit01(x[g]));
            if (lane == 0)
                g_xbitsT[((g & (KK - 1)) >> 5) * BB + (g >> 12)] = w;
        }
    }
    __threadfence();
    __syncthreads();
    if (t == 0) atomicAdd(&g_pack_arrive, 1);

    // ---------------- prologue: first tile's rows (overlap the wait) -------
    const uint32_t* mp = masks + (size_t)(slab * TILES * 32) * OO + omega * 32 + lane;
    uint32_t v[32];
    #pragma unroll
    for (int r = 0; r < 32; r++) v[r] = mp[(size_t)r * OO];

    // ---------------- grid barrier: all x bits published --------------------
    while (*(volatile int*)&g_pack_arrive < NBLK) __nanosleep(32);
    __threadfence();
    __syncthreads();                       // whole block past the spin
    if (t == 0) {
        int e = atomicAdd(&g_pack_exit, 1);
        if (e == NBLK - 1) { g_pack_exit = 0; g_pack_arrive = 0; }  // reset
    }

    // ---------------- mainloop: 16 tiles of 32x32 bits ----------------------
    uint32_t acc[32];
    #pragma unroll
    for (int i = 0; i < 32; i++) acc[i] = 0;

    #pragma unroll 1
    for (int kt = 0; kt < TILES; kt++) {
        // ballot each staged row into an o-bit word
        uint32_t wb[32];
        #pragma unroll
        for (int r = 0; r < 32; r++)
            wb[r] = __ballot_sync(0xFFFFFFFFu, bit01(v[r]));

        // prefetch next tile (independent of wb; overlaps transpose+popc)
        if (kt < TILES - 1) {
            const uint32_t* np = mp + (size_t)((kt + 1) * 32) * OO;
            #pragma unroll
            for (int r = 0; r < 32; r++) v[r] = np[(size_t)r * OO];
        }

        // in-register 32x32 bit transpose: X = k-bits of column o
        uint32_t X = 0;
        #pragma unroll
        for (int r = 0; r < 32; r++)
            X |= ((wb[r] >> lane) & 1u) << r;

        // popc vs all 64 batches, 16-bit packed accumulate (<=512 per slab)
        const int kw = slab * TILES + kt;
        const uint4* xp = reinterpret_cast<const uint4*>(&g_xbitsT[kw * BB]);
        #pragma unroll
        for (int i = 0; i < 16; i++) {
            uint4 q = xp[i];              // batches 4i .. 4i+3 (broadcast)
            acc[2 * i]     += __popc(X ^ q.x) + (__popc(X ^ q.y) << 16);
            acc[2 * i + 1] += __popc(X ^ q.z) + (__popc(X ^ q.w) << 16);
        }
    }

    // ---------------- partial store (coalesced per pair-row) ----------------
    #pragma unroll
    for (int i = 0; i < 32; i++)
        g_partial[(slab * 32 + i) * OO + o] = acc[i];
    __threadfence();

    // ---------------- finisher: 8th slab-warp of this omega reduces ---------
    int old = 0;
    if (lane == 0) old = atomicAdd(&g_ocnt[omega], 1);
    old = __shfl_sync(0xFFFFFFFFu, old, 0);
    if (old == NSLAB - 1) {
        __threadfence();                   // acquire partials
        const int th = thr[o];
        #pragma unroll 1
        for (int i = 0; i < 32; i++) {     // batch pair (2i, 2i+1)
            int s = 0;
            #pragma unroll
            for (int sl = 0; sl < NSLAB; sl++)
                s += (int)g_partial[(sl * 32 + i) * OO + o];
            const int lo = s & 0xFFFF;     // hamming for batch 2i
            const int hi = s >> 16;        // hamming for batch 2i+1
            out[(size_t)(2 * i) * OO + o]     = ((KK - lo) > th) ? 1.0f : 0.0f;
            out[(size_t)(2 * i + 1) * OO + o] = ((KK - hi) > th) ? 1.0f : 0.0f;
        }
        if (lane == 0) g_ocnt[omega] = 0;  // reset for next replay
    }
}

// ---------------------------------------------------------------------------
extern "C" void kernel_launch(void* const* d_in, const int* in_sizes, int n_in,
                              void* d_out, int out_size) {
    // Identify inputs by element count (robust to ordering)
    const void* x     = d_in[0];
    const void* masks = d_in[1];
    const int*  thr   = (const int*)d_in[2];
    for (int i = 0; i < n_in; i++) {
        if      (in_sizes[i] == KK * OO) masks = d_in[i];
        else if (in_sizes[i] == BB * KK) x     = d_in[i];
        else if (in_sizes[i] == OO)      thr   = (const int*)d_in[i];
    }

    xnor_bitgemm_kernel<<<NBLK, 128>>>((const uint32_t*)x, (const uint32_t*)masks,
                                       thr, (float*)d_out);
}

// round 13
// speedup vs baseline: 1.8488x; 1.8488x over previous
#include <cuda_runtime.h>
#include <cstdint>

// Problem constants
#define BB 64       // batch
#define KK 4096     // dim_in
#define OO 4096     // dim_out
#define OT 16       // output columns per strip
#define NSTRIP (OO / OT)    // 256
#define SLABS  4            // k-split
#define SKW    32           // kw per slab (1024 k-rows)
#define CKW    8            // kw per chunk
#define NCH    (SKW / CKW)  // 4 chunks per slab

// x bits, transposed: [kw][b]
__device__ uint32_t g_xbitsT[(KK / 32) * BB];             // 32 KB
// partial popc sums: [slab][strip][b][OT]
__device__ uint32_t g_partial[SLABS * NSTRIP * BB * OT];  // 4 MB
// strip completion counters (self-resetting; zero at load)
__device__ int g_scnt[NSTRIP];

// Robust 0/1 extraction: int32 {0,1} (bit 0) or float32 {0.0f,1.0f} (bit 23).
__device__ __forceinline__ uint32_t bit01(uint32_t w) {
    return (w | (w >> 23)) & 1u;
}

// ---------------------------------------------------------------------------
// Pack x via warp ballot: one thread per element (proven R9 kernel).
// ---------------------------------------------------------------------------
__global__ void __launch_bounds__(256) pack_x_kernel(const uint32_t* __restrict__ x) {
    const int g = blockIdx.x * 256 + threadIdx.x;   // 0..262143 -> (b, k)
    const uint32_t w = __ballot_sync(0xFFFFFFFFu, bit01(x[g]));
    if ((threadIdx.x & 31) == 0)
        g_xbitsT[((g & (KK - 1)) >> 5) * BB + (g >> 12)] = w;
}

// ---------------------------------------------------------------------------
// Partial+epilogue kernel: 1024 blocks (256 strips x 4 slabs) x 256 threads.
// Warp-specialized: warps 0-3 produce (stream+pack mask chunks into ping-pong
// tiles), warps 4-7 consume (XNOR-popcount vs x bits). One sync per chunk.
// Last slab-block per strip reduces partials, thresholds, writes output.
// ---------------------------------------------------------------------------
__global__ void __launch_bounds__(256) xnor_partial_kernel(
    const uint32_t* __restrict__ masks,  // [KK][OO] 0/1 words
    const int*      __restrict__ thr,    // [OO] int32
    float*          __restrict__ out)    // [BB][OO] float32 0/1
{
    __shared__ __align__(16) uint32_t tile[2][CKW * OT];  // 2 x 512B ping-pong
    __shared__ int s_last;

    const int t     = threadIdx.x;
    const int lane  = t & 31;
    const int warp  = t >> 5;
    const int strip = blockIdx.x & (NSTRIP - 1);
    const int slab  = blockIdx.x >> 8;
    const int o0    = strip * OT;
    const int kw0   = slab * SKW;

    // ---- producer: pack chunk c (8 kw x 16 cols) into tile[buf] -----------
    auto pack = [&](int c, int buf) {
        const int col = t & 15;
        const int kwl = t >> 4;              // 0..7 (t < 128)
        const uint32_t* bp =
            masks + (size_t)((kw0 + c * CKW + kwl) * 32) * OO + o0 + col;
        uint32_t w = 0;
        #pragma unroll
        for (int j = 0; j < 32; j++)
            w |= bit01(bp[(size_t)j * OO]) << j;
        tile[buf][kwl * OT + col] = w;
    };

    // prologue: first chunk
    if (t < 128) pack(0, 0);
    __syncthreads();

    // consumer mapping: warps 4..7 -> cw 0..3
    const int cw    = warp - 4;
    const int bhalf = cw & 1;
    const int os0   = cw >> 1;          // handles osets os0 and os0+2
    const int b     = bhalf * 32 + lane;

    int acc[8] = {0, 0, 0, 0, 0, 0, 0, 0};

    for (int c = 0; c < NCH; c++) {
        if (t < 128) {
            if (c + 1 < NCH) pack(c + 1, (c + 1) & 1);
        } else {
            const uint4* tb = reinterpret_cast<const uint4*>(tile[c & 1]);
            uint32_t xr[CKW];
            #pragma unroll
            for (int j = 0; j < CKW; j++)
                xr[j] = g_xbitsT[(kw0 + c * CKW + j) * BB + b];
            #pragma unroll
            for (int j = 0; j < CKW; j++) {
                const uint32_t xv = xr[j];
                uint4 m0 = tb[j * 4 + os0];        // broadcast LDS.128
                uint4 m1 = tb[j * 4 + os0 + 2];
                acc[0] += __popc(xv ^ m0.x);
                acc[1] += __popc(xv ^ m0.y);
                acc[2] += __popc(xv ^ m0.z);
                acc[3] += __popc(xv ^ m0.w);
                acc[4] += __popc(xv ^ m1.x);
                acc[5] += __popc(xv ^ m1.y);
                acc[6] += __popc(xv ^ m1.z);
                acc[7] += __popc(xv ^ m1.w);
            }
        }
        __syncthreads();
    }

    // ---- consumer partial store: [slab][strip][b][o] ----------------------
    if (t >= 128) {
        uint32_t* pp = &g_partial[(((size_t)slab * NSTRIP + strip) * BB + b) * OT];
        *reinterpret_cast<uint4*>(pp + os0 * 4) =
            make_uint4(acc[0], acc[1], acc[2], acc[3]);
        *reinterpret_cast<uint4*>(pp + (os0 + 2) * 4) =
            make_uint4(acc[4], acc[5], acc[6], acc[7]);
    }
    __threadfence();
    __syncthreads();

    // ---- last slab-block of this strip does the epilogue ------------------
    if (t == 0) s_last = (atomicAdd(&g_scnt[strip], 1) == SLABS - 1);
    __syncthreads();

    if (s_last) {
        if (t == 0) g_scnt[strip] = 0;    // reset for next graph replay
        __threadfence();                   // acquire all slabs' partials
        const int o_l = t & 15;
        const int o   = o0 + o_l;
        const int th  = thr[o];
        #pragma unroll
        for (int i = 0; i < 4; i++) {
            const int bb = (t >> 4) + i * 16;
            int s = 0;
            #pragma unroll
            for (int sl = 0; sl < SLABS; sl++)
                s += (int)g_partial[(((size_t)sl * NSTRIP + strip) * BB + bb) * OT + o_l];
            out[(size_t)bb * OO + o] = ((KK - s) > th) ? 1.0f : 0.0f;
        }
    }
}

// ---------------------------------------------------------------------------
extern "C" void kernel_launch(void* const* d_in, const int* in_sizes, int n_in,
                              void* d_out, int out_size) {
    // Identify inputs by element count (robust to ordering)
    const void* x     = d_in[0];
    const void* masks = d_in[1];
    const int*  thr   = (const int*)d_in[2];
    for (int i = 0; i < n_in; i++) {
        if      (in_sizes[i] == KK * OO) masks = d_in[i];
        else if (in_sizes[i] == BB * KK) x     = d_in[i];
        else if (in_sizes[i] == OO)      thr   = (const int*)d_in[i];
    }

    pack_x_kernel<<<(BB * KK) / 256, 256>>>((const uint32_t*)x);
    xnor_partial_kernel<<<NSTRIP * SLABS, 256>>>((const uint32_t*)masks,
                                                 thr, (float*)d_out);
}

// round 14
// speedup vs baseline: 1.9172x; 1.0370x over previous
#include <cuda_runtime.h>
#include <cstdint>

// Problem constants
#define BB 64       // batch
#define KK 4096     // dim_in
#define OO 4096     // dim_out
#define OT 16       // output columns per strip
#define NSTRIP (OO / OT)    // 256
#define SLABS  4            // k-split
#define SKW    32           // kw per slab (1024 k-rows)

// x bits, transposed: [kw][b]
__device__ uint32_t g_xbitsT[(KK / 32) * BB];             // 32 KB
// partial popc sums: [slab][strip][b][OT]
__device__ uint32_t g_partial[SLABS * NSTRIP * BB * OT];  // 4 MB
// strip completion counters (self-resetting; zero at load)
__device__ int g_scnt[NSTRIP];

// Robust 0/1 extraction: int32 {0,1} (bit 0) or float32 {0.0f,1.0f} (bit 23).
__device__ __forceinline__ uint32_t bit01(uint32_t w) {
    return (w | (w >> 23)) & 1u;
}

// ---------------------------------------------------------------------------
// Pack x via warp ballot: one thread per element (proven R9 kernel).
// ---------------------------------------------------------------------------
__global__ void __launch_bounds__(256) pack_x_kernel(const uint32_t* __restrict__ x) {
    const int g = blockIdx.x * 256 + threadIdx.x;   // 0..262143 -> (b, k)
    const uint32_t w = __ballot_sync(0xFFFFFFFFu, bit01(x[g]));
    if ((threadIdx.x & 31) == 0)
        g_xbitsT[((g & (KK - 1)) >> 5) * BB + (g >> 12)] = w;
}

// ---------------------------------------------------------------------------
// Partial kernel with fused epilogue: 1024 blocks x 256 threads.
// Slab-major indexing: strip = bid>>2, slab = bid&3 (strip's 4 slab-blocks
// launch adjacently -> land on different SMs; co-resident blocks differ in
// strip, desynchronizing their phase barriers).
//   phase 1: pack [1024 k-rows x 16 cols] into a 2KB bit tile (one sync)
//   phase 2: XNOR-popcount vs x bits, store partial sums
//   finisher: 4th-arriving slab block reduces partials + thresholds + writes.
// ---------------------------------------------------------------------------
__global__ void __launch_bounds__(256) xnor_partial_kernel(
    const uint32_t* __restrict__ masks,  // [KK][OO] 0/1 words
    const int*      __restrict__ thr,    // [OO] int32
    float*          __restrict__ out)    // [BB][OO] float32 0/1
{
    __shared__ uint32_t tile[SKW * OT];   // 2 KB, layout [kw][o]
    __shared__ int s_last;

    const int t     = threadIdx.x;
    const int strip = blockIdx.x >> 2;
    const int slab  = blockIdx.x & (SLABS - 1);
    const int o0    = strip * OT;
    const int kw0   = slab * SKW;

    // ---------------- phase 1: pack mask slab-strip into shared bits -------
    // thread -> (op = column pair 0..7, kwl = 0..31)
    {
        const int op  = t & 7;
        const int kwl = t >> 3;
        const uint2* base = reinterpret_cast<const uint2*>(
            masks + (size_t)((kw0 + kwl) * 32) * OO + o0 + op * 2);
        uint32_t a0 = 0, a1 = 0;
        #pragma unroll 8
        for (int j = 0; j < 32; j++) {
            uint2 m = base[(size_t)j * (OO / 2)];
            a0 |= bit01(m.x) << j;
            a1 |= bit01(m.y) << j;
        }
        *reinterpret_cast<uint2*>(&tile[kwl * OT + op * 2]) = make_uint2(a0, a1);
    }
    __syncthreads();

    // ---------------- phase 2: XNOR popcount over the slab ------------------
    const int lane = t & 31;
    const int warp = t >> 5;
    const int half = warp & 1;        // which 32 batches
    const int oset = warp >> 1;       // 0..3 -> 4 columns each
    const int b    = half * 32 + lane;

    int acc[4] = {0, 0, 0, 0};
    const uint4* t4 = reinterpret_cast<const uint4*>(tile);

    #pragma unroll
    for (int ck = 0; ck < SKW / 8; ck++) {
        uint32_t xr[8];
        #pragma unroll
        for (int j = 0; j < 8; j++)
            xr[j] = g_xbitsT[(kw0 + ck * 8 + j) * BB + b];

        #pragma unroll
        for (int j = 0; j < 8; j++) {
            const uint32_t xv = xr[j];
            uint4 m = t4[(ck * 8 + j) * 4 + oset];   // broadcast
            acc[0] += __popc(xv ^ m.x);
            acc[1] += __popc(xv ^ m.y);
            acc[2] += __popc(xv ^ m.z);
            acc[3] += __popc(xv ^ m.w);
        }
    }

    // partial store: [slab][strip][b][oset*4..+3]
    uint32_t* pp = &g_partial[(((size_t)slab * NSTRIP + strip) * BB + b) * OT + oset * 4];
    *reinterpret_cast<uint4*>(pp) =
        make_uint4((uint32_t)acc[0], (uint32_t)acc[1],
                   (uint32_t)acc[2], (uint32_t)acc[3]);
    __threadfence();
    __syncthreads();

    // ---------------- finisher: last slab-block of this strip ---------------
    if (t == 0) s_last = (atomicAdd(&g_scnt[strip], 1) == SLABS - 1);
    __syncthreads();

    if (s_last) {
        if (t == 0) g_scnt[strip] = 0;    // reset for next graph replay
        __threadfence();                   // acquire all slabs' partials
        const int o_l = t & 15;
        const int o   = o0 + o_l;
        const int th  = thr[o];
        #pragma unroll
        for (int i = 0; i < 4; i++) {
            const int bb = (t >> 4) + i * 16;
            int s = 0;
            #pragma unroll
            for (int sl = 0; sl < SLABS; sl++)
                s += (int)g_partial[(((size_t)sl * NSTRIP + strip) * BB + bb) * OT + o_l];
            out[(size_t)bb * OO + o] = ((KK - s) > th) ? 1.0f : 0.0f;
        }
    }
}

// ---------------------------------------------------------------------------
extern "C" void kernel_launch(void* const* d_in, const int* in_sizes, int n_in,
                              void* d_out, int out_size) {
    // Identify inputs by element count (robust to ordering)
    const void* x     = d_in[0];
    const void* masks = d_in[1];
    const int*  thr   = (const int*)d_in[2];
    for (int i = 0; i < n_in; i++) {
        if      (in_sizes[i] == KK * OO) masks = d_in[i];
        else if (in_sizes[i] == BB * KK) x     = d_in[i];
        else if (in_sizes[i] == OO)      thr   = (const int*)d_in[i];
    }

    pack_x_kernel<<<(BB * KK) / 256, 256>>>((const uint32_t*)x);
    xnor_partial_kernel<<<NSTRIP * SLABS, 256>>>((const uint32_t*)masks,
                                                 thr, (float*)d_out);
}